// round 9
// baseline (speedup 1.0000x reference)
#include <cuda_runtime.h>
#include <stdint.h>
#include <math.h>

// Per-block partial sums (written unconditionally every call -> no zeroing needed).
__device__ double g_part_lcc[512][3];
__device__ double g_part_aux[444][2];
__device__ unsigned int g_count = 0;  // self-resetting arrival counter

#define TOTAL_BLOCKS 1024u

__device__ __forceinline__ float warp_redf(float v) {
#pragma unroll
    for (int o = 16; o > 0; o >>= 1) v += __shfl_down_sync(0xffffffffu, v, o);
    return v;
}
__device__ __forceinline__ double warp_redd(double v) {
#pragma unroll
    for (int o = 16; o > 0; o >>= 1) v += __shfl_down_sync(0xffffffffu, v, o);
    return v;
}

__device__ __forceinline__ void cp4(unsigned int dst, const float* src, int srcsize) {
    asm volatile("cp.async.ca.shared.global [%0], [%1], 4, %2;"
                 :: "r"(dst), "l"(src), "r"(srcsize) : "memory");
}
#define CP_COMMIT() asm volatile("cp.async.commit_group;" ::: "memory")
#define CP_WAIT2()  asm volatile("cp.async.wait_group 2;" ::: "memory")

#define TW 32
#define TH 16
#define HW 36       // TW + 4 halo
#define HH 20       // TH + 4 halo
#define SLICE (HH * HW)   // 720
#define DEPTH 4

// ---------------------------------------------------------------------------
// Mega kernel. Even blockIdx.x -> LCC tile (cp.async-pipelined 5x5x5 box-mean
// + reduction, ONE barrier per z-slice), odd -> streaming aux reductions.
// Last block to arrive reduces partials and writes the scalar.
// ---------------------------------------------------------------------------
__global__ __launch_bounds__(512, 2) void mega_kernel(
    const float* __restrict__ F0, const float* __restrict__ F0g,
    const float* __restrict__ I0, const float* __restrict__ I0R,
    const float* __restrict__ I1, const float* __restrict__ I1R,
    const float* __restrict__ S0, const float* __restrict__ S0g,
    const float* __restrict__ S1, const float* __restrict__ S1g,
    float* __restrict__ out)
{
    __shared__ float bufA[DEPTH][SLICE];   // 11520 B
    __shared__ float bufB[DEPTH][SLICE];   // 11520 B
    __shared__ float rA[2][HH][TW];        // 5120 B
    __shared__ float rB[2][HH][TW];        // 5120 B
    __shared__ float redf[16][3];
    __shared__ double redd[16][2];
    __shared__ unsigned s_last;

    const int b = blockIdx.x;
    const int tid = threadIdx.x;
    const int lane = tid & 31, wid = tid >> 5;

    if (b & 1) {
        // ---------------- aux path: streaming reductions ----------------
        const int ab = b >> 1;
        if (ab < 444) {
            // byte-balanced split: reg 264 blocks, tversky 90 + 90
            int task, abl, nblk;
            if (ab < 264)      { task = 0; abl = ab;       nblk = 264; }
            else if (ab < 354) { task = 1; abl = ab - 264; nblk = 90;  }
            else               { task = 2; abl = ab - 354; nblk = 90;  }
            const int gid = abl * 512 + tid;
            const int stride = nblk * 512;

            float f0 = 0.f, f1 = 0.f;
            if (task == 0) {
                const float4* __restrict__ a = (const float4*)F0;
                const float4* __restrict__ c = (const float4*)F0g;
                const int n4 = 12582912 / 4;
#pragma unroll 4
                for (int i = gid; i < n4; i += stride) {
                    const float4 va = a[i], vb = c[i];
                    const float d0 = vb.x - va.x, d1 = vb.y - va.y;
                    const float d2 = vb.z - va.z, d3 = vb.w - va.w;
                    f0 += (d0 * d0 + d1 * d1) + (d2 * d2 + d3 * d3);
                }
            } else {
                const float4* __restrict__ a = (const float4*)(task == 1 ? S0 : S1);
                const float4* __restrict__ c = (const float4*)(task == 1 ? S0g : S1g);
                const int n4 = 4194304 / 4;
#pragma unroll 4
                for (int i = gid; i < n4; i += stride) {
                    const float4 va = a[i], vb = c[i];
                    f0 += ((va.x + vb.x) + (va.y + vb.y)) + ((va.z + vb.z) + (va.w + vb.w));
                    f1 += (va.x * vb.x + va.y * vb.y) + (va.z * vb.z + va.w * vb.w);
                }
            }
            double s0 = (double)f0, s1 = (double)f1;
            s0 = warp_redd(s0); s1 = warp_redd(s1);
            if (lane == 0) { redd[wid][0] = s0; redd[wid][1] = s1; }
            __syncthreads();
            if (wid == 0) {
                double v0 = (lane < 16) ? redd[lane][0] : 0.0;
                double v1 = (lane < 16) ? redd[lane][1] : 0.0;
                v0 = warp_redd(v0); v1 = warp_redd(v1);
                if (lane == 0) { g_part_aux[ab][0] = v0; g_part_aux[ab][1] = v1; }
            }
        }
    } else {
        // ---------------- LCC path ----------------
        const int lb = b >> 1;                 // 0..511
        const int tile = lb & 127;
        const int bi = lb >> 7;                // pair*2 + batch
        const int batch = bi & 1;
        const int pair = bi >> 1;

        const float* __restrict__ gt = pair ? I1 : I0;
        const float* __restrict__ pr = pair ? I1R : I0R;

        const int wt = tile & 3;
        const int ht = (tile >> 2) & 7;
        const int ck = tile >> 5;
        const int w0 = wt * TW, h0 = ht * TH, d0 = ck * 32;
        const long base = (long)batch * (128L * 128L * 128L);

        const int tx = tid & 31, ty = tid >> 5;

        // per-thread load slots (slice-invariant except z term)
        const int j0 = tid;
        const int j1 = tid + 512;
        const int hh0 = j0 / HW, ww0 = j0 - hh0 * HW;
        const int hh1 = j1 / HW, ww1 = j1 - hh1 * HW;
        const int gh0 = h0 + hh0 - 2, gw0 = w0 + ww0 - 2;
        const int gh1 = h0 + hh1 - 2, gw1 = w0 + ww1 - 2;
        const bool pv0 = ((unsigned)gh0 < 128u) && ((unsigned)gw0 < 128u);
        const bool pv1 = (j1 < SLICE) && ((unsigned)gh1 < 128u) && ((unsigned)gw1 < 128u);
        const long po0 = base + (pv0 ? ((long)gh0 * 128 + gw0) : 0L);
        const long po1 = base + (pv1 ? ((long)gh1 * 128 + gw1) : 0L);
        const bool has1 = (j1 < SLICE);

        const unsigned int aB = (unsigned int)__cvta_generic_to_shared(&bufA[0][0]);
        const unsigned int bB = (unsigned int)__cvta_generic_to_shared(&bufB[0][0]);
        const unsigned int da0 = aB + j0 * 4, db0 = bB + j0 * 4;
        const unsigned int da1 = aB + j1 * 4, db1 = bB + j1 * 4;

        // rings + center delay + accumulators
        float qA0 = 0, qA1 = 0, qA2 = 0, qA3 = 0, qA4 = 0;
        float qB0 = 0, qB1 = 0, qB2 = 0, qB3 = 0, qB4 = 0;
        float cA0 = 0, cA1 = 0, cA2 = 0;
        float cB0 = 0, cB1 = 0, cB2 = 0;
        float aN = 0.f, aG = 0.f, aP = 0.f;

        // issue copies for slice d (abs), into ring buffer k
        auto issue_slice = [&](int d, int k) {
            const int dcl = d < 0 ? 0 : (d > 127 ? 127 : d);
            const long zo = (long)dcl * 16384;
            const bool dv = ((unsigned)d < 128u);
            const unsigned int ko = (unsigned int)k * (SLICE * 4);
            const int sz0 = (dv && pv0) ? 4 : 0;
            cp4(da0 + ko, gt + po0 + zo, sz0);
            cp4(db0 + ko, pr + po0 + zo, sz0);
            if (has1) {
                const int sz1 = (dv && pv1) ? 4 : 0;
                cp4(da1 + ko, gt + po1 + zo, sz1);
                cp4(db1 + ko, pr + po1 + zo, sz1);
            }
        };

        // prologue: slices 0,1,2 (abs d0-2 .. d0), one group each
        issue_slice(d0 - 2, 0); CP_COMMIT();
        issue_slice(d0 - 1, 1); CP_COMMIT();
        issue_slice(d0,     2); CP_COMMIT();

        const int ci = (ty + 2) * HW + (tx + 2);  // center slot for this thread

        for (int it = 0; it < 36; ++it) {
            CP_WAIT2();            // this thread's copies for slice `it` done
            __syncthreads();       // everyone's copies landed; prev readers done
            if (it < 33) issue_slice(d0 + 1 + it, (it + 3) & 3);
            CP_COMMIT();           // commit every iteration (keeps group count aligned)

            // --- col stage for slice j = it-1 (reads rA[(it-1)&1]) ---
            if (it >= 1) {
                const int pp = (it - 1) & 1;
                const float nA = ((rA[pp][ty][tx] + rA[pp][ty + 1][tx]) +
                                  (rA[pp][ty + 2][tx] + rA[pp][ty + 3][tx])) + rA[pp][ty + 4][tx];
                const float nB = ((rB[pp][ty][tx] + rB[pp][ty + 1][tx]) +
                                  (rB[pp][ty + 2][tx] + rB[pp][ty + 3][tx])) + rB[pp][ty + 4][tx];
                qA0 = qA1; qA1 = qA2; qA2 = qA3; qA3 = qA4; qA4 = nA;
                qB0 = qB1; qB1 = qB2; qB2 = qB3; qB3 = qB4; qB4 = nB;
                if (it - 1 >= 4) {
                    const float zA = ((qA0 + qA1) + (qA2 + qA3)) + qA4;
                    const float zB = ((qB0 + qB1) + (qB2 + qB3)) + qB4;
                    const float dA = fmaf(zA, -(1.0f / 125.0f), cA2);
                    const float dB = fmaf(zB, -(1.0f / 125.0f), cB2);
                    aN = fmaf(dA, dB, aN);
                    aG = fmaf(dA, dA, aG);
                    aP = fmaf(dB, dB, aP);
                }
            }

            // --- row stage for slice `it` (writes rA[it&1], pushes center) ---
            {
                const int k = it & 3, pp = it & 1;
                const float* __restrict__ sa = bufA[k];
                const float* __restrict__ sb = bufB[k];
#pragma unroll 2
                for (int i = tid; i < HH * TW; i += 512) {
                    const int hh = i >> 5, w = i & 31;
                    const int o = hh * HW + w;
                    rA[pp][hh][w] = ((sa[o] + sa[o + 1]) + (sa[o + 2] + sa[o + 3])) + sa[o + 4];
                    rB[pp][hh][w] = ((sb[o] + sb[o + 1]) + (sb[o + 2] + sb[o + 3])) + sb[o + 4];
                }
                cA2 = cA1; cA1 = cA0; cA0 = sa[ci];
                cB2 = cB1; cB1 = cB0; cB0 = sb[ci];
            }
        }
        // epilogue: col stage for slice 35 (rA[1] written by all threads at it=35)
        __syncthreads();
        {
            const float nA = ((rA[1][ty][tx] + rA[1][ty + 1][tx]) +
                              (rA[1][ty + 2][tx] + rA[1][ty + 3][tx])) + rA[1][ty + 4][tx];
            const float nB = ((rB[1][ty][tx] + rB[1][ty + 1][tx]) +
                              (rB[1][ty + 2][tx] + rB[1][ty + 3][tx])) + rB[1][ty + 4][tx];
            qA0 = qA1; qA1 = qA2; qA2 = qA3; qA3 = qA4; qA4 = nA;
            qB0 = qB1; qB1 = qB2; qB2 = qB3; qB3 = qB4; qB4 = nB;
            const float zA = ((qA0 + qA1) + (qA2 + qA3)) + qA4;
            const float zB = ((qB0 + qB1) + (qB2 + qB3)) + qB4;
            const float dA = fmaf(zA, -(1.0f / 125.0f), cA2);
            const float dB = fmaf(zB, -(1.0f / 125.0f), cB2);
            aN = fmaf(dA, dB, aN);
            aG = fmaf(dA, dA, aG);
            aP = fmaf(dB, dB, aP);
        }

        aN = warp_redf(aN); aG = warp_redf(aG); aP = warp_redf(aP);
        if (lane == 0) { redf[wid][0] = aN; redf[wid][1] = aG; redf[wid][2] = aP; }
        __syncthreads();
        if (wid == 0) {
            float vN = (lane < 16) ? redf[lane][0] : 0.f;
            float vG = (lane < 16) ? redf[lane][1] : 0.f;
            float vP = (lane < 16) ? redf[lane][2] : 0.f;
            vN = warp_redf(vN); vG = warp_redf(vG); vP = warp_redf(vP);
            if (lane == 0) {
                g_part_lcc[lb][0] = (double)vN;
                g_part_lcc[lb][1] = (double)vG;
                g_part_lcc[lb][2] = (double)vP;
            }
        }
    }

    // ---------------- arrival + last-block finalization ----------------
    __syncthreads();
    if (tid == 0) {
        __threadfence();
        const unsigned old = atomicAdd(&g_count, 1u);
        const unsigned last = (old == TOTAL_BLOCKS - 1u);
        s_last = last;
        if (last) g_count = 0u;  // self-reset for next graph replay
    }
    __syncthreads();
    if (!s_last) return;

    __shared__ double facc[11];
    if (tid < 11) facc[tid] = 0.0;
    __syncthreads();
    {
        double vN = g_part_lcc[tid][0];
        double vG = g_part_lcc[tid][1];
        double vP = g_part_lcc[tid][2];
        const int pair = tid >> 8;  // warp-uniform
        vN = warp_redd(vN); vG = warp_redd(vG); vP = warp_redd(vP);
        if (lane == 0) {
            atomicAdd(&facc[1 + 3 * pair], vN);
            atomicAdd(&facc[2 + 3 * pair], vG);
            atomicAdd(&facc[3 + 3 * pair], vP);
        }
    }
    if (tid < 444) {
        const int task = (tid < 264) ? 0 : (tid < 354 ? 1 : 2);
        const double v0 = g_part_aux[tid][0];
        const double v1 = g_part_aux[tid][1];
        if (task == 0) {
            atomicAdd(&facc[0], v0);
        } else {
            atomicAdd(&facc[7 + 2 * (task - 1)], v0);
            atomicAdd(&facc[8 + 2 * (task - 1)], v1);
        }
    }
    __syncthreads();
    if (tid == 0) {
        double r = sqrt(facc[0]) / 12582912.0;  // reg_field_loss
#pragma unroll
        for (int k = 0; k < 2; ++k) {
            double num = facc[1 + 3 * k];
            num *= num;
            double den = facc[2 + 3 * k] * facc[3 + 3 * k];
            den = den > 1e-5 ? den : 1e-5;
            r += 10.0 * (-(num / den) / 4194304.0);  // lcc
            double ta = facc[7 + 2 * k];
            ta = ta > 1e-5 ? ta : 1e-5;
            r += 10.0 * (-(facc[8 + 2 * k] / ta));   // tversky
        }
        out[0] = (float)r;
    }
}

extern "C" void kernel_launch(void* const* d_in, const int* in_sizes, int n_in,
                              void* d_out, int out_size) {
    const float* F0  = (const float*)d_in[0];
    const float* F0g = (const float*)d_in[1];
    const float* I0  = (const float*)d_in[2];
    const float* I0R = (const float*)d_in[3];
    const float* I1  = (const float*)d_in[4];
    const float* I1R = (const float*)d_in[5];
    const float* S0  = (const float*)d_in[6];
    const float* S0g = (const float*)d_in[7];
    const float* S1  = (const float*)d_in[8];
    const float* S1g = (const float*)d_in[9];

    mega_kernel<<<TOTAL_BLOCKS, 512>>>(F0, F0g, I0, I0R, I1, I1R,
                                       S0, S0g, S1, S1g, (float*)d_out);
}

// round 10
// speedup vs baseline: 1.0599x; 1.0599x over previous
#include <cuda_runtime.h>
#include <stdint.h>
#include <math.h>

// Per-block partial sums (written unconditionally every call -> no zeroing needed).
__device__ double g_part_lcc[512][3];
__device__ double g_part_aux[444][2];
__device__ unsigned int g_count = 0;  // self-resetting arrival counter

#define TOTAL_BLOCKS 1024u

__device__ __forceinline__ float warp_redf(float v) {
#pragma unroll
    for (int o = 16; o > 0; o >>= 1) v += __shfl_down_sync(0xffffffffu, v, o);
    return v;
}
__device__ __forceinline__ double warp_redd(double v) {
#pragma unroll
    for (int o = 16; o > 0; o >>= 1) v += __shfl_down_sync(0xffffffffu, v, o);
    return v;
}

// 16-byte cp.async with zero-fill when srcsize==0
__device__ __forceinline__ void cp16(unsigned int dst, const float* src, int srcsize) {
    asm volatile("cp.async.cg.shared.global [%0], [%1], 16, %2;"
                 :: "r"(dst), "l"(src), "r"(srcsize) : "memory");
}
#define CP_COMMIT() asm volatile("cp.async.commit_group;" ::: "memory")
#define CP_WAIT2()  asm volatile("cp.async.wait_group 2;" ::: "memory")

#define TW 32
#define TH 16
#define SW 40       // padded smem row: w0-4 .. w0+35 (16B aligned slots)
#define HH 20       // TH + 4 halo
#define SLICE (HH * SW)   // 800 floats
#define DEPTH 4
#define NOPS 400    // 20 rows * 10 slots * 2 arrays

// ---------------------------------------------------------------------------
// Mega kernel. Even blockIdx.x -> LCC tile (vectorized cp.async-pipelined
// 5x5x5 box-mean + reduction, ONE barrier per z-slice), odd -> streaming aux.
// Last block to arrive reduces partials and writes the scalar.
// ---------------------------------------------------------------------------
__global__ __launch_bounds__(512, 2) void mega_kernel(
    const float* __restrict__ F0, const float* __restrict__ F0g,
    const float* __restrict__ I0, const float* __restrict__ I0R,
    const float* __restrict__ I1, const float* __restrict__ I1R,
    const float* __restrict__ S0, const float* __restrict__ S0g,
    const float* __restrict__ S1, const float* __restrict__ S1g,
    float* __restrict__ out)
{
    __shared__ float bufA[DEPTH][SLICE];   // 12800 B
    __shared__ float bufB[DEPTH][SLICE];   // 12800 B
    __shared__ float rA[2][HH][TW];        // 5120 B
    __shared__ float rB[2][HH][TW];        // 5120 B
    __shared__ float redf[16][3];
    __shared__ double redd[16][2];
    __shared__ unsigned s_last;

    const int b = blockIdx.x;
    const int tid = threadIdx.x;
    const int lane = tid & 31, wid = tid >> 5;

    if (b & 1) {
        // ---------------- aux path: streaming reductions ----------------
        const int ab = b >> 1;
        if (ab < 444) {
            // byte-balanced split: reg 264 blocks, tversky 90 + 90
            int task, abl, nblk;
            if (ab < 264)      { task = 0; abl = ab;       nblk = 264; }
            else if (ab < 354) { task = 1; abl = ab - 264; nblk = 90;  }
            else               { task = 2; abl = ab - 354; nblk = 90;  }
            const int gid = abl * 512 + tid;
            const int stride = nblk * 512;

            float f0 = 0.f, f1 = 0.f;
            if (task == 0) {
                const float4* __restrict__ a = (const float4*)F0;
                const float4* __restrict__ c = (const float4*)F0g;
                const int n4 = 12582912 / 4;
#pragma unroll 4
                for (int i = gid; i < n4; i += stride) {
                    const float4 va = a[i], vb = c[i];
                    const float d0 = vb.x - va.x, d1 = vb.y - va.y;
                    const float d2 = vb.z - va.z, d3 = vb.w - va.w;
                    f0 += (d0 * d0 + d1 * d1) + (d2 * d2 + d3 * d3);
                }
            } else {
                const float4* __restrict__ a = (const float4*)(task == 1 ? S0 : S1);
                const float4* __restrict__ c = (const float4*)(task == 1 ? S0g : S1g);
                const int n4 = 4194304 / 4;
#pragma unroll 4
                for (int i = gid; i < n4; i += stride) {
                    const float4 va = a[i], vb = c[i];
                    f0 += ((va.x + vb.x) + (va.y + vb.y)) + ((va.z + vb.z) + (va.w + vb.w));
                    f1 += (va.x * vb.x + va.y * vb.y) + (va.z * vb.z + va.w * vb.w);
                }
            }
            double s0 = (double)f0, s1 = (double)f1;
            s0 = warp_redd(s0); s1 = warp_redd(s1);
            if (lane == 0) { redd[wid][0] = s0; redd[wid][1] = s1; }
            __syncthreads();
            if (wid == 0) {
                double v0 = (lane < 16) ? redd[lane][0] : 0.0;
                double v1 = (lane < 16) ? redd[lane][1] : 0.0;
                v0 = warp_redd(v0); v1 = warp_redd(v1);
                if (lane == 0) { g_part_aux[ab][0] = v0; g_part_aux[ab][1] = v1; }
            }
        }
    } else {
        // ---------------- LCC path ----------------
        const int lb = b >> 1;                 // 0..511
        const int tile = lb & 127;
        const int bi = lb >> 7;                // pair*2 + batch
        const int batch = bi & 1;
        const int pair = bi >> 1;

        const float* __restrict__ gt = pair ? I1 : I0;
        const float* __restrict__ pr = pair ? I1R : I0R;

        const int wt = tile & 3;
        const int ht = (tile >> 2) & 7;
        const int ck = tile >> 5;
        const int w0 = wt * TW, h0 = ht * TH, d0 = ck * 32;
        const long base = (long)batch * (128L * 128L * 128L);

        const int tx = tid & 31, ty = tid >> 5;

        // --- per-thread vector load slot: one 16B cp.async per slice ---
        // op o in [0, 400): arr = o>=200, j = o%200, rr = j/10 (row), q = j%10
        const bool hasop = (tid < NOPS);
        const int o = hasop ? tid : 0;
        const int arr = (o >= 200) ? 1 : 0;
        const int j = o - arr * 200;
        const int rr = j / 10, q = j - rr * 10;
        const int gh = h0 + rr - 2;
        const int gw4 = w0 - 4 + q * 4;
        const bool pvalid = hasop && ((unsigned)gh < 128u) && ((unsigned)gw4 <= 124u);
        const long po = base + (pvalid ? ((long)gh * 128 + gw4) : 0L);
        const float* const srcbase = arr ? pr : gt;

        const unsigned int aB = (unsigned int)__cvta_generic_to_shared(&bufA[0][0]);
        const unsigned int bB = (unsigned int)__cvta_generic_to_shared(&bufB[0][0]);
        const unsigned int dst0 = (arr ? bB : aB) + (unsigned int)(rr * SW + q * 4) * 4u;

        // rings + center delay + accumulators
        float qA0 = 0, qA1 = 0, qA2 = 0, qA3 = 0, qA4 = 0;
        float qB0 = 0, qB1 = 0, qB2 = 0, qB3 = 0, qB4 = 0;
        float cA0 = 0, cA1 = 0, cA2 = 0;
        float cB0 = 0, cB1 = 0, cB2 = 0;
        float aN = 0.f, aG = 0.f, aP = 0.f;

        // issue this thread's copy for slice d (abs), into ring buffer k
        auto issue_slice = [&](int d, int k) {
            if (hasop) {
                const int dcl = d < 0 ? 0 : (d > 127 ? 127 : d);
                const bool dv = ((unsigned)d < 128u);
                const int sz = (dv && pvalid) ? 16 : 0;
                cp16(dst0 + (unsigned int)k * (SLICE * 4u), srcbase + po + (long)dcl * 16384, sz);
            }
        };

        // prologue: slices 0,1,2 (abs d0-2 .. d0), one group each
        issue_slice(d0 - 2, 0); CP_COMMIT();
        issue_slice(d0 - 1, 1); CP_COMMIT();
        issue_slice(d0,     2); CP_COMMIT();

        const int ci = (ty + 2) * SW + (tx + 4);  // center slot for this thread

        for (int it = 0; it < 36; ++it) {
            CP_WAIT2();            // this thread's copies for slice `it` done
            __syncthreads();       // everyone's copies landed; prev readers done
            if (it < 33) issue_slice(d0 + 1 + it, (it + 3) & 3);
            CP_COMMIT();           // commit every iteration (keeps group count aligned)

            // --- col stage for slice jslc = it-1 (reads rA[(it-1)&1]) ---
            if (it >= 1) {
                const int pp = (it - 1) & 1;
                const float nA = ((rA[pp][ty][tx] + rA[pp][ty + 1][tx]) +
                                  (rA[pp][ty + 2][tx] + rA[pp][ty + 3][tx])) + rA[pp][ty + 4][tx];
                const float nB = ((rB[pp][ty][tx] + rB[pp][ty + 1][tx]) +
                                  (rB[pp][ty + 2][tx] + rB[pp][ty + 3][tx])) + rB[pp][ty + 4][tx];
                qA0 = qA1; qA1 = qA2; qA2 = qA3; qA3 = qA4; qA4 = nA;
                qB0 = qB1; qB1 = qB2; qB2 = qB3; qB3 = qB4; qB4 = nB;
                if (it - 1 >= 4) {
                    const float zA = ((qA0 + qA1) + (qA2 + qA3)) + qA4;
                    const float zB = ((qB0 + qB1) + (qB2 + qB3)) + qB4;
                    const float dA = fmaf(zA, -(1.0f / 125.0f), cA2);
                    const float dB = fmaf(zB, -(1.0f / 125.0f), cB2);
                    aN = fmaf(dA, dB, aN);
                    aG = fmaf(dA, dA, aG);
                    aP = fmaf(dB, dB, aP);
                }
            }

            // --- row stage for slice `it` (writes rA[it&1], pushes center) ---
            {
                const int k = it & 3, pp = it & 1;
                const float* __restrict__ sa = bufA[k];
                const float* __restrict__ sb = bufB[k];
#pragma unroll 2
                for (int i = tid; i < HH * TW; i += 512) {
                    const int hh = i >> 5, w = i & 31;
                    const int oo = hh * SW + w + 2;   // padded start is w0-4; output w center at +4
                    rA[pp][hh][w] = ((sa[oo] + sa[oo + 1]) + (sa[oo + 2] + sa[oo + 3])) + sa[oo + 4];
                    rB[pp][hh][w] = ((sb[oo] + sb[oo + 1]) + (sb[oo + 2] + sb[oo + 3])) + sb[oo + 4];
                }
                cA2 = cA1; cA1 = cA0; cA0 = sa[ci];
                cB2 = cB1; cB1 = cB0; cB0 = sb[ci];
            }
        }
        // epilogue: col stage for slice 35 (rA[1] written by all threads at it=35)
        __syncthreads();
        {
            const float nA = ((rA[1][ty][tx] + rA[1][ty + 1][tx]) +
                              (rA[1][ty + 2][tx] + rA[1][ty + 3][tx])) + rA[1][ty + 4][tx];
            const float nB = ((rB[1][ty][tx] + rB[1][ty + 1][tx]) +
                              (rB[1][ty + 2][tx] + rB[1][ty + 3][tx])) + rB[1][ty + 4][tx];
            qA0 = qA1; qA1 = qA2; qA2 = qA3; qA3 = qA4; qA4 = nA;
            qB0 = qB1; qB1 = qB2; qB2 = qB3; qB3 = qB4; qB4 = nB;
            const float zA = ((qA0 + qA1) + (qA2 + qA3)) + qA4;
            const float zB = ((qB0 + qB1) + (qB2 + qB3)) + qB4;
            const float dA = fmaf(zA, -(1.0f / 125.0f), cA2);
            const float dB = fmaf(zB, -(1.0f / 125.0f), cB2);
            aN = fmaf(dA, dB, aN);
            aG = fmaf(dA, dA, aG);
            aP = fmaf(dB, dB, aP);
        }

        aN = warp_redf(aN); aG = warp_redf(aG); aP = warp_redf(aP);
        if (lane == 0) { redf[wid][0] = aN; redf[wid][1] = aG; redf[wid][2] = aP; }
        __syncthreads();
        if (wid == 0) {
            float vN = (lane < 16) ? redf[lane][0] : 0.f;
            float vG = (lane < 16) ? redf[lane][1] : 0.f;
            float vP = (lane < 16) ? redf[lane][2] : 0.f;
            vN = warp_redf(vN); vG = warp_redf(vG); vP = warp_redf(vP);
            if (lane == 0) {
                g_part_lcc[lb][0] = (double)vN;
                g_part_lcc[lb][1] = (double)vG;
                g_part_lcc[lb][2] = (double)vP;
            }
        }
    }

    // ---------------- arrival + last-block finalization ----------------
    __syncthreads();
    if (tid == 0) {
        __threadfence();
        const unsigned old = atomicAdd(&g_count, 1u);
        const unsigned last = (old == TOTAL_BLOCKS - 1u);
        s_last = last;
        if (last) g_count = 0u;  // self-reset for next graph replay
    }
    __syncthreads();
    if (!s_last) return;

    __shared__ double facc[11];
    if (tid < 11) facc[tid] = 0.0;
    __syncthreads();
    {
        double vN = g_part_lcc[tid][0];
        double vG = g_part_lcc[tid][1];
        double vP = g_part_lcc[tid][2];
        const int pair = tid >> 8;  // warp-uniform
        vN = warp_redd(vN); vG = warp_redd(vG); vP = warp_redd(vP);
        if (lane == 0) {
            atomicAdd(&facc[1 + 3 * pair], vN);
            atomicAdd(&facc[2 + 3 * pair], vG);
            atomicAdd(&facc[3 + 3 * pair], vP);
        }
    }
    if (tid < 444) {
        const int task = (tid < 264) ? 0 : (tid < 354 ? 1 : 2);
        const double v0 = g_part_aux[tid][0];
        const double v1 = g_part_aux[tid][1];
        if (task == 0) {
            atomicAdd(&facc[0], v0);
        } else {
            atomicAdd(&facc[7 + 2 * (task - 1)], v0);
            atomicAdd(&facc[8 + 2 * (task - 1)], v1);
        }
    }
    __syncthreads();
    if (tid == 0) {
        double r = sqrt(facc[0]) / 12582912.0;  // reg_field_loss
#pragma unroll
        for (int k = 0; k < 2; ++k) {
            double num = facc[1 + 3 * k];
            num *= num;
            double den = facc[2 + 3 * k] * facc[3 + 3 * k];
            den = den > 1e-5 ? den : 1e-5;
            r += 10.0 * (-(num / den) / 4194304.0);  // lcc
            double ta = facc[7 + 2 * k];
            ta = ta > 1e-5 ? ta : 1e-5;
            r += 10.0 * (-(facc[8 + 2 * k] / ta));   // tversky
        }
        out[0] = (float)r;
    }
}

extern "C" void kernel_launch(void* const* d_in, const int* in_sizes, int n_in,
                              void* d_out, int out_size) {
    const float* F0  = (const float*)d_in[0];
    const float* F0g = (const float*)d_in[1];
    const float* I0  = (const float*)d_in[2];
    const float* I0R = (const float*)d_in[3];
    const float* I1  = (const float*)d_in[4];
    const float* I1R = (const float*)d_in[5];
    const float* S0  = (const float*)d_in[6];
    const float* S0g = (const float*)d_in[7];
    const float* S1  = (const float*)d_in[8];
    const float* S1g = (const float*)d_in[9];

    mega_kernel<<<TOTAL_BLOCKS, 512>>>(F0, F0g, I0, I0R, I1, I1R,
                                       S0, S0g, S1, S1g, (float*)d_out);
}